// round 4
// baseline (speedup 1.0000x reference)
#include <cuda_runtime.h>
#include <cuda_fp16.h>
#include <float.h>
#include <stdint.h>

#define NCODES   4096
#define CDIM     64
#define NTOK     65536
#define HW       4096
#define M_TILE   128
#define N_CHUNK  64
#define NCHUNKS  64
#define THREADS  256
#define SCALE    64.0f
#define ESQ_SCALE 4096.0f

#define B_STRIDE 144   // bytes per B row: 64 halves (128B) + 16B pad -> conflict-free ldmatrix

// ---- smem byte offsets ----
#define OFF_ZS      0        // 64*132*4 = 33792
#define OFF_ESQ     33792    // 16384
#define OFF_B0      50176    // 9216
#define OFF_B1      59392    // 9216  (ends 68608)
#define OFF_ZSQTOK  68608    // 512
#define OFF_RED     69120    // 1024
#define OFF_SIDX    70144    // 512
#define OFF_FBCNT   70656    // 4
#define OFF_FBLIST  70660    // 512
// resolve arrays overlay the B buffers after the main loop:
#define OFF_SB0     50176    // 8*128 floats
#define OFF_SI0     54272    // 8*128 ints
#define OFF_SB1     58368    // 8*128 floats (ends 62464)
#define SMEM_TOTAL  71680

__device__ float  g_esq[NCODES];
__device__ __half g_embh[NCODES * CDIM];

__device__ __forceinline__ uint32_t smem_u32(const void* p) {
    uint32_t a;
    asm("{ .reg .u64 t; cvta.to.shared.u64 t, %1; cvt.u32.u64 %0, t; }" : "=r"(a) : "l"(p));
    return a;
}
__device__ __forceinline__ void cp16(uint32_t dst, const void* src) {
    asm volatile("cp.async.cg.shared.global [%0], [%1], 16;" :: "r"(dst), "l"(src));
}
__device__ __forceinline__ void cp_commit() {
    asm volatile("cp.async.commit_group;");
}
template <int N>
__device__ __forceinline__ void cp_wait() {
    asm volatile("cp.async.wait_group %0;" :: "n"(N));
}
__device__ __forceinline__ void mma16816(float* c, const uint32_t* a, uint32_t b0, uint32_t b1) {
    asm volatile(
        "mma.sync.aligned.m16n8k16.row.col.f32.f16.f16.f32 "
        "{%0,%1,%2,%3}, {%4,%5,%6,%7}, {%8,%9}, {%0,%1,%2,%3};"
        : "+f"(c[0]), "+f"(c[1]), "+f"(c[2]), "+f"(c[3])
        : "r"(a[0]), "r"(a[1]), "r"(a[2]), "r"(a[3]), "r"(b0), "r"(b1));
}
__device__ __forceinline__ void ldmx4(uint32_t& r0, uint32_t& r1, uint32_t& r2, uint32_t& r3,
                                      uint32_t a) {
    asm volatile("ldmatrix.sync.aligned.m8n8.x4.shared.b16 {%0,%1,%2,%3}, [%4];"
        : "=r"(r0), "=r"(r1), "=r"(r2), "=r"(r3) : "r"(a));
}
__device__ __forceinline__ uint32_t pack2h(float v0, float v1) {
    __half h0 = __float2half_rn(v0);
    __half h1 = __float2half_rn(v1);
    return (uint32_t)__half_as_ushort(h0) | ((uint32_t)__half_as_ushort(h1) << 16);
}

// prep: ||e||^2 per code + fp16 codebook (scaled by 64). one warp per code.
__global__ void prep_kernel(const float* __restrict__ emb) {
    int warp = (blockIdx.x * blockDim.x + threadIdx.x) >> 5;
    int lane = threadIdx.x & 31;
    if (warp >= NCODES) return;
    const float* row = emb + (size_t)warp * CDIM;
    float v0 = row[lane], v1 = row[lane + 32];
    g_embh[warp * CDIM + lane]      = __float2half_rn(v0 * SCALE);
    g_embh[warp * CDIM + lane + 32] = __float2half_rn(v1 * SCALE);
    float s = v0 * v0 + v1 * v1;
    #pragma unroll
    for (int off = 16; off; off >>= 1) s += __shfl_xor_sync(0xffffffffu, s, off);
    if (lane == 0) g_esq[warp] = s;
}

__global__ __launch_bounds__(THREADS, 2)
void vq_kernel(const float* __restrict__ z,
               const float* __restrict__ emb,
               float* __restrict__ out) {
    extern __shared__ char sm[];
    float* zs     = (float*)(sm + OFF_ZS);       // [64][132]
    float* esq_s  = (float*)(sm + OFF_ESQ);      // [4096]
    float* zsqtok = (float*)(sm + OFF_ZSQTOK);   // [128]
    float* red    = (float*)(sm + OFF_RED);      // [256]
    int*   sidx   = (int*)(sm + OFF_SIDX);       // [128]
    int*   fbcnt  = (int*)(sm + OFF_FBCNT);
    int*   fblist = (int*)(sm + OFF_FBLIST);
    float* sb0    = (float*)(sm + OFF_SB0);
    int*   si0    = (int*)(sm + OFF_SI0);
    float* sb1    = (float*)(sm + OFF_SB1);

    const uint32_t sb = smem_u32(sm);
    const int tid  = threadIdx.x;
    const int lane = tid & 31;
    const int wid  = tid >> 5;
    const int grp  = lane >> 2;
    const int tid4 = lane & 3;
    const int mwarp = wid >> 1;
    const int nw    = wid & 1;

    const int n0  = blockIdx.x * M_TILE;
    const int bb  = n0 >> 12;
    const int hw0 = n0 & (HW - 1);
    const float* zb = z + (size_t)bb * CDIM * HW + hw0;

    // ---- prologue: cp.async chunk 0 -> B0 ----
    const int crow = tid >> 3, cpart = tid & 7;   // covers rows 0..31; +32 on 2nd iter
    {
        const __half* src = g_embh;
        #pragma unroll
        for (int r = 0; r < 2; r++) {
            int row = crow + r * 32;
            cp16(sb + OFF_B0 + row * B_STRIDE + cpart * 16, src + row * 64 + cpart * 8);
        }
        cp_commit();
    }

    // ---- stage z (scaled) + per-token ||zs||^2 partials ----
    {
        const int mytok = tid & 127;
        const int c0 = tid >> 7;
        float zp = 0.f;
        #pragma unroll
        for (int k = 0; k < 32; k++) {
            int c = c0 + 2 * k;
            float v = zb[(size_t)c * HW + mytok] * SCALE;
            zs[c * 132 + mytok] = v;
            zp = fmaf(v, v, zp);
        }
        red[tid] = zp;
    }
    // ---- stage esq (scaled) + local max ----
    float lm = 0.f;
    #pragma unroll
    for (int j = 0; j < 16; j++) {
        float v = g_esq[tid + j * 256] * ESQ_SCALE;
        esq_s[tid + j * 256] = v;
        lm = fmaxf(lm, v);
    }
    __syncthreads();
    if (tid < 128) zsqtok[tid] = red[tid] + red[tid + 128];
    __syncthreads();
    red[tid] = lm;
    __syncthreads();
    #pragma unroll
    for (int s2 = 128; s2 > 0; s2 >>= 1) {
        if (tid < s2) red[tid] = fmaxf(red[tid], red[tid + s2]);
        __syncthreads();
    }
    // red[0] = emax2 (scaled); persists through main loop

    // ---- A fragments (fp16 hi of scaled z) ----
    uint32_t Ah[2][4][4];
    #pragma unroll
    for (int m = 0; m < 2; m++) {
        int r0 = mwarp * 32 + m * 16 + grp;
        #pragma unroll
        for (int s = 0; s < 4; s++) {
            int kb = 2 * tid4 + 16 * s;
            Ah[m][s][0] = pack2h(zs[kb * 132 + r0],           zs[(kb + 1) * 132 + r0]);
            Ah[m][s][1] = pack2h(zs[kb * 132 + r0 + 8],       zs[(kb + 1) * 132 + r0 + 8]);
            Ah[m][s][2] = pack2h(zs[(kb + 8) * 132 + r0],     zs[(kb + 9) * 132 + r0]);
            Ah[m][s][3] = pack2h(zs[(kb + 8) * 132 + r0 + 8], zs[(kb + 9) * 132 + r0 + 8]);
        }
    }

    const int lrow  = (lane & 7) + ((lane >> 4) & 1) * 8;
    const int lkoff = ((lane >> 3) & 1) * 16;
    const uint32_t baddr = (uint32_t)(nw * 32 + lrow) * B_STRIDE + lkoff;
    const uint32_t bbase[2] = { sb + OFF_B0, sb + OFF_B1 };
    const uint32_t boff[2]  = { OFF_B0, OFF_B1 };

    float b0v[4], b1v[4];
    int   b0i[4];
    #pragma unroll
    for (int g = 0; g < 4; g++) { b0v[g] = FLT_MAX; b1v[g] = FLT_MAX; b0i[g] = 0; }

    for (int ch = 0; ch < NCHUNKS; ch++) {
        const int buf = ch & 1;
        if (ch < NCHUNKS - 1) {
            const __half* src = g_embh + (size_t)(ch + 1) * N_CHUNK * CDIM;
            #pragma unroll
            for (int r = 0; r < 2; r++) {
                int row = crow + r * 32;
                cp16(sb + boff[buf ^ 1] + row * B_STRIDE + cpart * 16, src + row * 64 + cpart * 8);
            }
            cp_commit();
            cp_wait<1>();
        } else {
            cp_wait<0>();
        }
        __syncthreads();

        float acc[2][4][4];
        #pragma unroll
        for (int m = 0; m < 2; m++)
            #pragma unroll
            for (int f = 0; f < 4; f++)
                #pragma unroll
                for (int r = 0; r < 4; r++) acc[m][f][r] = 0.f;

        #pragma unroll
        for (int s = 0; s < 4; s++) {
            #pragma unroll
            for (int fp = 0; fp < 2; fp++) {
                uint32_t h0, h1, h2, h3;
                ldmx4(h0, h1, h2, h3, bbase[buf] + baddr + fp * (16 * B_STRIDE) + s * 32);
                mma16816(acc[0][2 * fp],     Ah[0][s], h0, h1);
                mma16816(acc[1][2 * fp],     Ah[1][s], h0, h1);
                mma16816(acc[0][2 * fp + 1], Ah[0][s], h2, h3);
                mma16816(acc[1][2 * fp + 1], Ah[1][s], h2, h3);
            }
        }

        // ---- epilogue: best2 tracking with chunk-min shortcut ----
        const int cb = ch * N_CHUNK + nw * 32;
        float2 ee[4];
        #pragma unroll
        for (int f = 0; f < 4; f++)
            ee[f] = *(const float2*)&esq_s[cb + f * 8 + 2 * tid4];

        #pragma unroll
        for (int m = 0; m < 2; m++) {
            #pragma unroll
            for (int h = 0; h < 2; h++) {
                const int g = m * 2 + h;
                float sv[8];
                #pragma unroll
                for (int f = 0; f < 4; f++) {
                    sv[2 * f]     = fmaf(acc[m][f][h * 2 + 0], -2.0f, ee[f].x);
                    sv[2 * f + 1] = fmaf(acc[m][f][h * 2 + 1], -2.0f, ee[f].y);
                }
                float mn = sv[0];
                #pragma unroll
                for (int j = 1; j < 8; j++) mn = fminf(mn, sv[j]);
                if (mn < b1v[g]) {
                    #pragma unroll
                    for (int jj = 0; jj < 8; jj++) {
                        float v = sv[jj];
                        if (v < b0v[g]) {
                            b1v[g] = b0v[g];
                            b0v[g] = v;
                            b0i[g] = cb + (jj >> 1) * 8 + 2 * tid4 + (jj & 1);
                        } else if (v < b1v[g]) {
                            b1v[g] = v;
                        }
                    }
                }
            }
        }
        __syncthreads();
    }

    // ---- dump per-thread state (overlay on B buffers) ----
    {
        const int slot = nw * 4 + tid4;
        #pragma unroll
        for (int g = 0; g < 4; g++) {
            int token = mwarp * 32 + (g >> 1) * 16 + grp + (g & 1) * 8;
            sb0[slot * 128 + token] = b0v[g];
            si0[slot * 128 + token] = b0i[g];
            sb1[slot * 128 + token] = b1v[g];
        }
    }
    if (tid == 0) *fbcnt = 0;
    const float emax2 = red[0];
    __syncthreads();

    // ---- resolve per token ----
    if (tid < 128) {
        const int t = tid;
        float gv = FLT_MAX; int gi = 0;
        #pragma unroll
        for (int s = 0; s < 8; s++) {
            float v = sb0[s * 128 + t];
            int   i = si0[s * 128 + t];
            if (v < gv || (v == gv && i < gi)) { gv = v; gi = i; }
        }
        const float thr = gv + 0.0041f * sqrtf(zsqtok[t] * emax2) + 32.0f;
        int cand[8], nc = 0;
        bool fb = false;
        #pragma unroll
        for (int s = 0; s < 8; s++) {
            if (sb1[s * 128 + t] <= thr) fb = true;
            if (sb0[s * 128 + t] <= thr) cand[nc++] = si0[s * 128 + t];
        }
        if (fb) {
            int p = atomicAdd(fbcnt, 1);
            fblist[p] = t;
        } else if (nc > 1) {
            float bd = FLT_MAX; int bi = 0;
            for (int j = 0; j < nc; j++) {
                int c = cand[j];
                const float4* e4 = (const float4*)(emb + (size_t)c * CDIM);
                float dot = 0.f;
                #pragma unroll
                for (int k4 = 0; k4 < 16; k4++) {
                    float4 e = __ldg(&e4[k4]);
                    dot = fmaf(zs[(4 * k4 + 0) * 132 + t], e.x, dot);
                    dot = fmaf(zs[(4 * k4 + 1) * 132 + t], e.y, dot);
                    dot = fmaf(zs[(4 * k4 + 2) * 132 + t], e.z, dot);
                    dot = fmaf(zs[(4 * k4 + 3) * 132 + t], e.w, dot);
                }
                float d = esq_s[c] - 128.0f * dot;
                if (d < bd || (d == bd && c < bi)) { bd = d; bi = c; }
            }
            sidx[t] = bi;
        } else {
            sidx[t] = gi;
        }
    }
    __syncthreads();

    // ---- fallback tokens: full fp32 rescan, CTA-cooperative ----
    const int nfb = *fbcnt;
    float* rv = red;                 // 8 floats
    int*   ri = (int*)(red + 8);     // 8 ints
    for (int fi = 0; fi < nfb; fi++) {
        const int tok = fblist[fi];
        float bv = FLT_MAX; int bi = 0;
        for (int c = tid; c < NCODES; c += THREADS) {
            const float4* e4 = (const float4*)(emb + (size_t)c * CDIM);
            float dot = 0.f;
            #pragma unroll
            for (int k4 = 0; k4 < 16; k4++) {
                float4 e = __ldg(&e4[k4]);
                dot = fmaf(zs[(4 * k4 + 0) * 132 + tok], e.x, dot);
                dot = fmaf(zs[(4 * k4 + 1) * 132 + tok], e.y, dot);
                dot = fmaf(zs[(4 * k4 + 2) * 132 + tok], e.z, dot);
                dot = fmaf(zs[(4 * k4 + 3) * 132 + tok], e.w, dot);
            }
            float d = esq_s[c] - 128.0f * dot;
            if (d < bv || (d == bv && c < bi)) { bv = d; bi = c; }
        }
        #pragma unroll
        for (int off = 16; off; off >>= 1) {
            float ov = __shfl_xor_sync(0xffffffffu, bv, off);
            int   oi = __shfl_xor_sync(0xffffffffu, bi, off);
            if (ov < bv || (ov == bv && oi < bi)) { bv = ov; bi = oi; }
        }
        if (lane == 0) { rv[wid] = bv; ri[wid] = bi; }
        __syncthreads();
        if (tid == 0) {
            float fv = rv[0]; int fidx = ri[0];
            #pragma unroll
            for (int w = 1; w < 8; w++)
                if (rv[w] < fv || (rv[w] == fv && ri[w] < fidx)) { fv = rv[w]; fidx = ri[w]; }
            sidx[tok] = fidx;
        }
        __syncthreads();
    }

    // ---- gather emb[idx], write transposed & coalesced (stage in zs region) ----
    float* st = zs;   // [128][65]
    for (int i = tid; i < M_TILE * CDIM; i += THREADS) {
        int tok = i >> 6, c = i & 63;
        st[tok * 65 + c] = emb[(size_t)sidx[tok] * CDIM + c];
    }
    __syncthreads();
    float* ob = out + (size_t)bb * CDIM * HW + hw0;
    for (int i = tid; i < CDIM * M_TILE; i += THREADS) {
        int c = i >> 7, tok = i & (M_TILE - 1);
        ob[(size_t)c * HW + tok] = st[tok * 65 + c];
    }
}

extern "C" void kernel_launch(void* const* d_in, const int* in_sizes, int n_in,
                              void* d_out, int out_size) {
    const float* z   = (const float*)d_in[0];
    const float* emb = (const float*)d_in[1];
    float* out = (float*)d_out;

    cudaFuncSetAttribute(vq_kernel, cudaFuncAttributeMaxDynamicSharedMemorySize, SMEM_TOTAL);

    prep_kernel<<<NCODES / 8, 256>>>(emb);
    vq_kernel<<<NTOK / M_TILE, THREADS, SMEM_TOTAL>>>(z, emb, out);
}

// round 5
// speedup vs baseline: 1.0272x; 1.0272x over previous
#include <cuda_runtime.h>
#include <cuda_fp16.h>
#include <float.h>
#include <stdint.h>

#define NCODES   4096
#define CDIM     64
#define NTOK     65536
#define HW       4096
#define M_TILE   128
#define N_CHUNK  128
#define NCHUNKS  32
#define THREADS  256
#define SCALE    64.0f
#define ESQ_SCALE 4096.0f

#define B_STRIDE 144   // bytes per row: 64 halves + 16B pad -> conflict-free ldmatrix

// ---- smem byte offsets ----
#define OFF_ZS      0        // 64*132*4 = 33792 (fp32 z, scaled; reused as gather stage)
#define OFF_ASM     33792    // 128*144 = 18432 fp16 A tile
#define OFF_ESQ     52224    // 16384
#define OFF_B0      68608    // 18432
#define OFF_B1      87040    // 18432 (ends 105472)
#define OFF_ZSQTOK  105472   // 512
#define OFF_RED     105984   // 1024
#define OFF_SIDX    107008   // 512
#define OFF_FBCNT   107520   // 16
#define OFF_FBLIST  107536   // 512
#define SMEM_TOTAL  108544
// resolve overlays (valid after main loop; inside B0/B1 region):
#define OFF_SB0     68608    // 8*128 floats
#define OFF_SI0     72704    // 8*128 ints
#define OFF_SB1     76800    // 8*128 floats

__device__ float  g_esq[NCODES];
__device__ __half g_embh[NCODES * CDIM];

__device__ __forceinline__ uint32_t smem_u32(const void* p) {
    uint32_t a;
    asm("{ .reg .u64 t; cvta.to.shared.u64 t, %1; cvt.u32.u64 %0, t; }" : "=r"(a) : "l"(p));
    return a;
}
__device__ __forceinline__ void cp16(uint32_t dst, const void* src) {
    asm volatile("cp.async.cg.shared.global [%0], [%1], 16;" :: "r"(dst), "l"(src));
}
__device__ __forceinline__ void cp_commit() { asm volatile("cp.async.commit_group;"); }
template <int N>
__device__ __forceinline__ void cp_wait() { asm volatile("cp.async.wait_group %0;" :: "n"(N)); }

__device__ __forceinline__ void mma16816(float* c, const uint32_t* a, uint32_t b0, uint32_t b1) {
    asm volatile(
        "mma.sync.aligned.m16n8k16.row.col.f32.f16.f16.f32 "
        "{%0,%1,%2,%3}, {%4,%5,%6,%7}, {%8,%9}, {%0,%1,%2,%3};"
        : "+f"(c[0]), "+f"(c[1]), "+f"(c[2]), "+f"(c[3])
        : "r"(a[0]), "r"(a[1]), "r"(a[2]), "r"(a[3]), "r"(b0), "r"(b1));
}
__device__ __forceinline__ void ldmx4(uint32_t& r0, uint32_t& r1, uint32_t& r2, uint32_t& r3,
                                      uint32_t a) {
    asm volatile("ldmatrix.sync.aligned.m8n8.x4.shared.b16 {%0,%1,%2,%3}, [%4];"
        : "=r"(r0), "=r"(r1), "=r"(r2), "=r"(r3) : "r"(a));
}
__device__ __forceinline__ uint32_t pack2h(float v0, float v1) {
    __half h0 = __float2half_rn(v0);
    __half h1 = __float2half_rn(v1);
    return (uint32_t)__half_as_ushort(h0) | ((uint32_t)__half_as_ushort(h1) << 16);
}

// prep: ||e||^2 per code + fp16 codebook (scaled by 64). one warp per code.
__global__ void prep_kernel(const float* __restrict__ emb) {
    int warp = (blockIdx.x * blockDim.x + threadIdx.x) >> 5;
    int lane = threadIdx.x & 31;
    if (warp >= NCODES) return;
    const float* row = emb + (size_t)warp * CDIM;
    float v0 = row[lane], v1 = row[lane + 32];
    g_embh[warp * CDIM + lane]      = __float2half_rn(v0 * SCALE);
    g_embh[warp * CDIM + lane + 32] = __float2half_rn(v1 * SCALE);
    float s = v0 * v0 + v1 * v1;
    #pragma unroll
    for (int off = 16; off; off >>= 1) s += __shfl_xor_sync(0xffffffffu, s, off);
    if (lane == 0) g_esq[warp] = s;
}

__global__ __launch_bounds__(THREADS, 2)
void vq_kernel(const float* __restrict__ z,
               const float* __restrict__ emb,
               float* __restrict__ out) {
    extern __shared__ char sm[];
    float* zs     = (float*)(sm + OFF_ZS);       // [64][132]
    float* esq_s  = (float*)(sm + OFF_ESQ);      // [4096]
    float* zsqtok = (float*)(sm + OFF_ZSQTOK);   // [128]
    float* red    = (float*)(sm + OFF_RED);      // [256]
    int*   sidx   = (int*)(sm + OFF_SIDX);       // [128]
    int*   fbcnt  = (int*)(sm + OFF_FBCNT);
    int*   fblist = (int*)(sm + OFF_FBLIST);
    float* sb0    = (float*)(sm + OFF_SB0);
    int*   si0    = (int*)(sm + OFF_SI0);
    float* sb1    = (float*)(sm + OFF_SB1);

    const uint32_t sb = smem_u32(sm);
    const int tid  = threadIdx.x;
    const int lane = tid & 31;
    const int wid  = tid >> 5;
    const int grp  = lane >> 2;
    const int tid4 = lane & 3;
    const int mwarp = wid >> 1;     // token rows mwarp*32..+31
    const int nw    = wid & 1;      // code cols nw*64..+63 within chunk

    const int n0  = blockIdx.x * M_TILE;
    const int bb  = n0 >> 12;
    const int hw0 = n0 & (HW - 1);
    const float* zb = z + (size_t)bb * CDIM * HW + hw0;

    // ---- prologue: cp.async chunk 0 -> B0 ----
    const int cpart = tid & 7;      // 16B part within row
    const int crow0 = tid >> 3;     // 0..31, rows +32,+64,+96
    {
        #pragma unroll
        for (int r = 0; r < 4; r++) {
            int row = crow0 + r * 32;
            cp16(sb + OFF_B0 + row * B_STRIDE + cpart * 16, g_embh + row * 64 + cpart * 8);
        }
        cp_commit();
    }

    // ---- stage z (scaled): fp32 to zs, fp16 pairs to Asm; ||z||^2 partials ----
    {
        const int tok  = tid & 127;
        const int half = tid >> 7;
        float zp = 0.f;
        #pragma unroll
        for (int j = 0; j < 16; j++) {
            int c = half * 32 + 2 * j;
            float v0 = zb[(size_t)c * HW + tok] * SCALE;
            float v1 = zb[(size_t)(c + 1) * HW + tok] * SCALE;
            zs[c * 132 + tok] = v0;
            zs[(c + 1) * 132 + tok] = v1;
            *(uint32_t*)(sm + OFF_ASM + tok * B_STRIDE + c * 2) = pack2h(v0, v1);
            zp = fmaf(v0, v0, fmaf(v1, v1, zp));
        }
        red[tid] = zp;
    }
    // ---- stage esq (scaled) + local max ----
    float lm = 0.f;
    #pragma unroll
    for (int j = 0; j < 16; j++) {
        float v = g_esq[tid + j * 256] * ESQ_SCALE;
        esq_s[tid + j * 256] = v;
        lm = fmaxf(lm, v);
    }
    __syncthreads();
    if (tid < 128) zsqtok[tid] = red[tid] + red[tid + 128];
    __syncthreads();
    red[tid] = lm;
    __syncthreads();
    #pragma unroll
    for (int s2 = 128; s2 > 0; s2 >>= 1) {
        if (tid < s2) red[tid] = fmaxf(red[tid], red[tid + s2]);
        __syncthreads();
    }
    const float emax2 = red[0];

    // ldmatrix lane addresses
    const uint32_t aaddr = sb + OFF_ASM
        + (uint32_t)(mwarp * 32 + (lane & 15)) * B_STRIDE + ((lane >> 4) & 1) * 16;
    const int lrow  = (lane & 7) + ((lane >> 4) & 1) * 8;
    const int lkoff = ((lane >> 3) & 1) * 16;
    const uint32_t bladdr = (uint32_t)(nw * 64 + lrow) * B_STRIDE + lkoff;
    const uint32_t boff[2] = { OFF_B0, OFF_B1 };

    float b0v[4], b1v[4];
    int   b0i[4];
    #pragma unroll
    for (int g = 0; g < 4; g++) { b0v[g] = FLT_MAX; b1v[g] = FLT_MAX; b0i[g] = 0; }

    for (int ch = 0; ch < NCHUNKS; ch++) {
        const int buf = ch & 1;
        if (ch < NCHUNKS - 1) {
            const __half* src = g_embh + (size_t)(ch + 1) * N_CHUNK * CDIM;
            #pragma unroll
            for (int r = 0; r < 4; r++) {
                int row = crow0 + r * 32;
                cp16(sb + boff[buf ^ 1] + row * B_STRIDE + cpart * 16, src + row * 64 + cpart * 8);
            }
            cp_commit();
            cp_wait<1>();
        } else {
            cp_wait<0>();
        }
        __syncthreads();

        float acc[2][8][4];
        #pragma unroll
        for (int m = 0; m < 2; m++)
            #pragma unroll
            for (int f = 0; f < 8; f++)
                #pragma unroll
                for (int r = 0; r < 4; r++) acc[m][f][r] = 0.f;

        const uint32_t bbuf = sb + boff[buf] + bladdr;
        #pragma unroll
        for (int s = 0; s < 4; s++) {
            uint32_t A0[4], A1[4];
            ldmx4(A0[0], A0[1], A0[2], A0[3], aaddr + s * 32);
            ldmx4(A1[0], A1[1], A1[2], A1[3], aaddr + 16 * B_STRIDE + s * 32);
            #pragma unroll
            for (int fp = 0; fp < 4; fp++) {
                uint32_t h0, h1, h2, h3;
                ldmx4(h0, h1, h2, h3, bbuf + fp * (16 * B_STRIDE) + s * 32);
                mma16816(acc[0][2 * fp],     A0, h0, h1);
                mma16816(acc[1][2 * fp],     A1, h0, h1);
                mma16816(acc[0][2 * fp + 1], A0, h2, h3);
                mma16816(acc[1][2 * fp + 1], A1, h2, h3);
            }
        }

        // ---- epilogue: chunk-min shortcut, recompute-on-hit best2 update ----
        const int cb = ch * N_CHUNK + nw * 64;
        float2 ee[8];
        #pragma unroll
        for (int f = 0; f < 8; f++)
            ee[f] = *(const float2*)&esq_s[cb + f * 8 + 2 * tid4];

        #pragma unroll
        for (int m = 0; m < 2; m++) {
            #pragma unroll
            for (int h = 0; h < 2; h++) {
                const int g = m * 2 + h;
                float mn = FLT_MAX;
                #pragma unroll
                for (int f = 0; f < 8; f++) {
                    mn = fminf(mn, fmaf(acc[m][f][h * 2 + 0], -2.0f, ee[f].x));
                    mn = fminf(mn, fmaf(acc[m][f][h * 2 + 1], -2.0f, ee[f].y));
                }
                if (mn < b1v[g]) {
                    #pragma unroll
                    for (int f = 0; f < 8; f++) {
                        #pragma unroll
                        for (int c = 0; c < 2; c++) {
                            float v = fmaf(acc[m][f][h * 2 + c], -2.0f, c ? ee[f].y : ee[f].x);
                            if (v < b0v[g]) {
                                b1v[g] = b0v[g];
                                b0v[g] = v;
                                b0i[g] = cb + f * 8 + 2 * tid4 + c;
                            } else if (v < b1v[g]) {
                                b1v[g] = v;
                            }
                        }
                    }
                }
            }
        }
        __syncthreads();
    }

    // ---- dump per-thread state (overlay on B buffers) ----
    {
        const int slot = nw * 4 + tid4;
        #pragma unroll
        for (int g = 0; g < 4; g++) {
            int token = mwarp * 32 + (g >> 1) * 16 + (g & 1) * 8 + grp;
            sb0[slot * 128 + token] = b0v[g];
            si0[slot * 128 + token] = b0i[g];
            sb1[slot * 128 + token] = b1v[g];
        }
    }
    if (tid == 0) *fbcnt = 0;
    __syncthreads();

    // ---- resolve per token ----
    if (tid < 128) {
        const int t = tid;
        float gv = FLT_MAX; int gi = 0;
        #pragma unroll
        for (int s = 0; s < 8; s++) {
            float v = sb0[s * 128 + t];
            int   i = si0[s * 128 + t];
            if (v < gv || (v == gv && i < gi)) { gv = v; gi = i; }
        }
        const float thr = gv + 0.0041f * sqrtf(zsqtok[t] * emax2) + 32.0f;
        int cand[8], nc = 0;
        bool fb = false;
        #pragma unroll
        for (int s = 0; s < 8; s++) {
            if (sb1[s * 128 + t] <= thr) fb = true;
            if (sb0[s * 128 + t] <= thr) cand[nc++] = si0[s * 128 + t];
        }
        if (fb) {
            int p = atomicAdd(fbcnt, 1);
            fblist[p] = t;
        } else if (nc > 1) {
            float bd = FLT_MAX; int bi = 0;
            for (int j = 0; j < nc; j++) {
                int c = cand[j];
                const float4* e4 = (const float4*)(emb + (size_t)c * CDIM);
                float dot = 0.f;
                #pragma unroll
                for (int k4 = 0; k4 < 16; k4++) {
                    float4 e = __ldg(&e4[k4]);
                    dot = fmaf(zs[(4 * k4 + 0) * 132 + t], e.x, dot);
                    dot = fmaf(zs[(4 * k4 + 1) * 132 + t], e.y, dot);
                    dot = fmaf(zs[(4 * k4 + 2) * 132 + t], e.z, dot);
                    dot = fmaf(zs[(4 * k4 + 3) * 132 + t], e.w, dot);
                }
                float d = esq_s[c] - 128.0f * dot;
                if (d < bd || (d == bd && c < bi)) { bd = d; bi = c; }
            }
            sidx[t] = bi;
        } else {
            sidx[t] = gi;
        }
    }
    __syncthreads();

    // ---- fallback tokens: full fp32 rescan, CTA-cooperative ----
    const int nfb = *fbcnt;
    float* rv = red;
    int*   ri = (int*)(red + 8);
    for (int fi = 0; fi < nfb; fi++) {
        const int tok = fblist[fi];
        float bv = FLT_MAX; int bi = 0;
        for (int c = tid; c < NCODES; c += THREADS) {
            const float4* e4 = (const float4*)(emb + (size_t)c * CDIM);
            float dot = 0.f;
            #pragma unroll
            for (int k4 = 0; k4 < 16; k4++) {
                float4 e = __ldg(&e4[k4]);
                dot = fmaf(zs[(4 * k4 + 0) * 132 + tok], e.x, dot);
                dot = fmaf(zs[(4 * k4 + 1) * 132 + tok], e.y, dot);
                dot = fmaf(zs[(4 * k4 + 2) * 132 + tok], e.z, dot);
                dot = fmaf(zs[(4 * k4 + 3) * 132 + tok], e.w, dot);
            }
            float d = esq_s[c] - 128.0f * dot;
            if (d < bv || (d == bv && c < bi)) { bv = d; bi = c; }
        }
        #pragma unroll
        for (int off = 16; off; off >>= 1) {
            float ov = __shfl_xor_sync(0xffffffffu, bv, off);
            int   oi = __shfl_xor_sync(0xffffffffu, bi, off);
            if (ov < bv || (ov == bv && oi < bi)) { bv = ov; bi = oi; }
        }
        if (lane == 0) { rv[wid] = bv; ri[wid] = bi; }
        __syncthreads();
        if (tid == 0) {
            float fv = rv[0]; int fidx = ri[0];
            #pragma unroll
            for (int w = 1; w < 8; w++)
                if (rv[w] < fv || (rv[w] == fv && ri[w] < fidx)) { fv = rv[w]; fidx = ri[w]; }
            sidx[tok] = fidx;
        }
        __syncthreads();
    }

    // ---- gather emb[idx], write transposed & coalesced (stage in zs region) ----
    float* st = zs;   // [128][65]
    for (int i = tid; i < M_TILE * CDIM; i += THREADS) {
        int tok = i >> 6, c = i & 63;
        st[tok * 65 + c] = emb[(size_t)sidx[tok] * CDIM + c];
    }
    __syncthreads();
    float* ob = out + (size_t)bb * CDIM * HW + hw0;
    for (int i = tid; i < CDIM * M_TILE; i += THREADS) {
        int c = i >> 7, tok = i & (M_TILE - 1);
        ob[(size_t)c * HW + tok] = st[tok * 65 + c];
    }
}

extern "C" void kernel_launch(void* const* d_in, const int* in_sizes, int n_in,
                              void* d_out, int out_size) {
    const float* z   = (const float*)d_in[0];
    const float* emb = (const float*)d_in[1];
    float* out = (float*)d_out;

    cudaFuncSetAttribute(vq_kernel, cudaFuncAttributeMaxDynamicSharedMemorySize, SMEM_TOTAL);

    prep_kernel<<<NCODES / 8, 256>>>(emb);
    vq_kernel<<<NTOK / M_TILE, THREADS, SMEM_TOTAL>>>(z, emb, out);
}